// round 2
// baseline (speedup 1.0000x reference)
#include <cuda_runtime.h>
#include <math.h>

#define NB   16
#define NC   256
#define NH   64
#define NW   64
#define NE   4
#define NTAP 9
#define SEXP (NC*NC*NTAP)   // 589824 weights per expert / per sample

// Scratch (device globals: allocation-free per harness rules)
__device__ float g_pooled[NB*NC];
__device__ float g_routing[NB*NE];
__device__ float g_weff[(size_t)NB*SEXP];   // 37.7 MB per-sample folded weights

// ---------------------------------------------------------------------------
// Kernel 1: global average pool  x[b,c,:,:] -> pooled[b,c]
// ---------------------------------------------------------------------------
__global__ void pool_kernel(const float* __restrict__ x) {
    int bc = blockIdx.x;                       // 0..NB*NC-1
    const float4* p = (const float4*)(x + (size_t)bc * NH * NW);
    float s = 0.f;
    for (int i = threadIdx.x; i < NH*NW/4; i += blockDim.x) {
        float4 v = p[i];
        s += v.x + v.y + v.z + v.w;
    }
    #pragma unroll
    for (int o = 16; o; o >>= 1) s += __shfl_xor_sync(0xffffffffu, s, o);
    __shared__ float red[4];
    if ((threadIdx.x & 31) == 0) red[threadIdx.x >> 5] = s;
    __syncthreads();
    if (threadIdx.x == 0) {
        float t = red[0] + red[1] + red[2] + red[3];
        g_pooled[bc] = t * (1.0f / (NH * NW));
    }
}

// ---------------------------------------------------------------------------
// Kernel 2: routing = sigmoid(pooled @ w_route^T + b_route)   [16,4]
// ---------------------------------------------------------------------------
__global__ void route_kernel(const float* __restrict__ wr, const float* __restrict__ br) {
    int t = threadIdx.x;
    if (t >= NB * NE) return;
    int b = t >> 2, e = t & 3;
    float acc = br[e];
    const float* pw = wr + e * NC;
    const float* pp = g_pooled + b * NC;
    #pragma unroll 8
    for (int c = 0; c < NC; ++c) acc = fmaf(pp[c], pw[c], acc);
    g_routing[t] = 1.f / (1.f + expf(-acc));
}

// ---------------------------------------------------------------------------
// Kernel 3: fold experts  W_eff[b] = sum_e routing[b,e] * W[e]
// ---------------------------------------------------------------------------
__global__ void fold_kernel(const float* __restrict__ we) {
    const int J = SEXP / 4;                    // float4 elements per expert
    int j = blockIdx.x * blockDim.x + threadIdx.x;
    if (j >= J) return;
    float4 w0 = ((const float4*)we)[j];
    float4 w1 = ((const float4*)we)[j + J];
    float4 w2 = ((const float4*)we)[j + 2*J];
    float4 w3 = ((const float4*)we)[j + 3*J];
    #pragma unroll
    for (int b = 0; b < NB; ++b) {
        float r0 = g_routing[b*4+0], r1 = g_routing[b*4+1];
        float r2 = g_routing[b*4+2], r3 = g_routing[b*4+3];
        float4 o;
        o.x = w0.x*r0 + w1.x*r1 + w2.x*r2 + w3.x*r3;
        o.y = w0.y*r0 + w1.y*r1 + w2.y*r2 + w3.y*r3;
        o.z = w0.z*r0 + w1.z*r1 + w2.z*r2 + w3.z*r3;
        o.w = w0.w*r0 + w1.w*r1 + w2.w*r2 + w3.w*r3;
        ((float4*)g_weff)[(size_t)b * J + j] = o;
    }
}

// ---------------------------------------------------------------------------
// Kernel 4: per-sample conv3x3 (pad 1) with folded weights + BN + SiLU.
// Implicit GEMM: M=64 out-channels x N=64 pixels (one image row) per block.
// 128 threads, register tile 4 (ch) x 8 (cols), K chunked by TK=8 in-channels.
// ---------------------------------------------------------------------------
#define TK 8
#define TM 64

__global__ __launch_bounds__(128, 4)
void conv_kernel(const float* __restrict__ x,
                 const float* __restrict__ gamma,
                 const float* __restrict__ beta,
                 const float* __restrict__ mean,
                 const float* __restrict__ var,
                 float* __restrict__ out) {
    // sA[(c*9+t)*65 + o]  : folded weights, padded row (65) -> conflict-free STS
    // sB[c*198 + r*66 + (1+w)] : input rows h-1..h+1, cols -1..64 (zero-padded)
    __shared__ float sA[TK * NTAP * 65];       // 4680 floats
    __shared__ float sB[TK * 3 * 66];          // 1584 floats

    const int ct  = blockIdx.x;                // channel tile 0..3
    const int h   = blockIdx.y;                // output row 0..63
    const int b   = blockIdx.z;                // batch 0..15
    const int tid = threadIdx.x;
    const int om  = tid & 15;                  // o-subtile: o = obase + om*4 + i
    const int cm  = tid >> 4;                  // col group:  w0 = cm*8
    const int obase = ct * TM;
    const int w0 = cm * 8;

    const float* gw = g_weff + (size_t)b * SEXP + (size_t)obase * (NC * NTAP);
    const float* gx = x + (size_t)b * NC * NH * NW;

    float acc[4][8];
    #pragma unroll
    for (int i = 0; i < 4; ++i)
        #pragma unroll
        for (int j = 0; j < 8; ++j) acc[i][j] = 0.f;

    for (int c0 = 0; c0 < NC; c0 += TK) {
        // --- fill sA: TK*9*64 = 4608 weights (coalesced LDG, conflict-free STS)
        for (int lin = tid; lin < TK * NTAP * TM; lin += 128) {
            int o   = lin / (TK * NTAP);
            int idx = lin - o * (TK * NTAP);   // idx = c*9 + t, 0..71
            sA[idx * 65 + o] = gw[(size_t)o * (NC * NTAP) + c0 * NTAP + idx];
        }
        // --- fill sB: TK channels x 3 halo rows x 66 cols (zero padding)
        for (int lin = tid; lin < TK * 3 * 66; lin += 128) {
            int c   = lin / 198;
            int rem = lin - c * 198;
            int r   = rem / 66;
            int j   = rem - r * 66;
            int hin = h + r - 1;
            int w   = j - 1;
            float v = 0.f;
            if ((unsigned)hin < NH && (unsigned)w < NW)
                v = gx[((size_t)(c0 + c) * NH + hin) * NW + w];
            sB[lin] = v;
        }
        __syncthreads();

        #pragma unroll 1
        for (int c = 0; c < TK; ++c) {
            float bv[3][10];
            #pragma unroll
            for (int r = 0; r < 3; ++r)
                #pragma unroll
                for (int j = 0; j < 10; ++j)
                    bv[r][j] = sB[c * 198 + r * 66 + w0 + j];
            #pragma unroll
            for (int t = 0; t < 9; ++t) {
                const int dh = t / 3, dw = t - dh * 3;
                float a0 = sA[(c * 9 + t) * 65 + om * 4 + 0];
                float a1 = sA[(c * 9 + t) * 65 + om * 4 + 1];
                float a2 = sA[(c * 9 + t) * 65 + om * 4 + 2];
                float a3 = sA[(c * 9 + t) * 65 + om * 4 + 3];
                #pragma unroll
                for (int j = 0; j < 8; ++j) {
                    float bb = bv[dh][dw + j];
                    acc[0][j] = fmaf(a0, bb, acc[0][j]);
                    acc[1][j] = fmaf(a1, bb, acc[1][j]);
                    acc[2][j] = fmaf(a2, bb, acc[2][j]);
                    acc[3][j] = fmaf(a3, bb, acc[3][j]);
                }
            }
        }
        __syncthreads();
    }

    // --- epilogue: BN (running stats) + SiLU, vectorized store
    #pragma unroll
    for (int i = 0; i < 4; ++i) {
        int o = obase + om * 4 + i;
        float inv = gamma[o] * rsqrtf(var[o] + 1e-5f);
        float add = beta[o] - mean[o] * inv;
        float* po = out + (((size_t)b * NC + o) * NH + h) * NW + w0;
        float tmp[8];
        #pragma unroll
        for (int j = 0; j < 8; ++j) {
            float z = acc[i][j] * inv + add;
            tmp[j] = z / (1.f + expf(-z));     // SiLU = z * sigmoid(z)
        }
        ((float4*)po)[0] = make_float4(tmp[0], tmp[1], tmp[2], tmp[3]);
        ((float4*)po)[1] = make_float4(tmp[4], tmp[5], tmp[6], tmp[7]);
    }
}

// ---------------------------------------------------------------------------
extern "C" void kernel_launch(void* const* d_in, const int* in_sizes, int n_in,
                              void* d_out, int out_size) {
    const float* x        = (const float*)d_in[0];  // [16,256,64,64]
    const float* w_route  = (const float*)d_in[1];  // [4,256]
    const float* b_route  = (const float*)d_in[2];  // [4]
    const float* w_expert = (const float*)d_in[3];  // [4,256,256,3,3]
    const float* bn_gamma = (const float*)d_in[4];  // [256]
    const float* bn_beta  = (const float*)d_in[5];
    const float* bn_mean  = (const float*)d_in[6];
    const float* bn_var   = (const float*)d_in[7];
    float* out = (float*)d_out;

    pool_kernel<<<NB * NC, 128>>>(x);
    route_kernel<<<1, 64>>>(w_route, b_route);
    fold_kernel<<<(SEXP / 4 + 255) / 256, 256>>>(w_expert);
    dim3 grid(NC / TM, NH, NB);
    conv_kernel<<<grid, 128>>>(x, bn_gamma, bn_beta, bn_mean, bn_var, out);
}

// round 4
// speedup vs baseline: 6.1692x; 6.1692x over previous
#include <cuda_runtime.h>
#include <math.h>
#include <stdint.h>

#define NB 16
#define NC 256
#define NH 64
#define NW 64
#define NTAP 9
#define SEXP (NC*NC*NTAP)
#define QP 66
#define QN (QP*QP)                /* 4356 padded pixels */
#define TILE_M 128
#define TILE_N 256
#define KC 32                     /* K chunk (channels) */
#define NSTEPS (NTAP*(NC/KC))     /* 72 */
#define ROWLEN 36                 /* 32 k + 4 pad floats */
#define STAGE_FLOATS ((TILE_M + TILE_N) * ROWLEN)   /* 13824 */
#define STAGES 3
#define SMEM_TOTAL (STAGES * STAGE_FLOATS * 4)      /* 165888 B */
#define QTILES ((QN + TILE_N - 1) / TILE_N)         /* 18 */

__device__ float g_pooled[NB*NC];
__device__ float g_routing[NB*4];
__device__ __align__(1024) float g_weff[(size_t)NB*NTAP*NC*NC];  // [b][t][o][c]
__device__ __align__(1024) float g_xpad[(size_t)NB*QN*NC];       // [b][q][c]

// ------------------------------------------------------------------ helpers
__device__ __forceinline__ uint32_t s2u(const void* p){
    uint32_t a;
    asm("{ .reg .u64 t; cvta.to.shared.u64 t, %1; cvt.u32.u64 %0, t; }" : "=r"(a) : "l"(p));
    return a;
}
__device__ __forceinline__ float to_tf32(float x){
    uint32_t r; asm("cvt.rna.tf32.f32 %0, %1;" : "=r"(r) : "f"(x));
    return __uint_as_float(r);
}
__device__ __forceinline__ void cp16(uint32_t dst, const void* src, int szbytes){
    asm volatile("cp.async.cg.shared.global [%0], [%1], 16, %2;"
                 :: "r"(dst), "l"(src), "r"(szbytes) : "memory");
}
__device__ __forceinline__ void cp_commit(){
    asm volatile("cp.async.commit_group;" ::: "memory");
}
template<int N> __device__ __forceinline__ void cp_wait(){
    asm volatile("cp.async.wait_group %0;" :: "n"(N) : "memory");
}
__device__ __forceinline__ void mma8(float* d, const float* a, const float* b){
    asm volatile("mma.sync.aligned.m16n8k8.row.col.f32.tf32.tf32.f32 "
        "{%0,%1,%2,%3}, {%4,%5,%6,%7}, {%8,%9}, {%0,%1,%2,%3};"
        : "+f"(d[0]), "+f"(d[1]), "+f"(d[2]), "+f"(d[3])
        : "r"(__float_as_uint(a[0])), "r"(__float_as_uint(a[1])),
          "r"(__float_as_uint(a[2])), "r"(__float_as_uint(a[3])),
          "r"(__float_as_uint(b[0])), "r"(__float_as_uint(b[1])));
}

// ------------------------------------------------------------------ prep
__global__ void pool_kernel(const float* __restrict__ x) {
    int bc = blockIdx.x;
    const float4* p = (const float4*)(x + (size_t)bc * NH * NW);
    float s = 0.f;
    for (int i = threadIdx.x; i < NH*NW/4; i += blockDim.x) {
        float4 v = p[i];
        s += v.x + v.y + v.z + v.w;
    }
    #pragma unroll
    for (int o = 16; o; o >>= 1) s += __shfl_xor_sync(0xffffffffu, s, o);
    __shared__ float red[4];
    if ((threadIdx.x & 31) == 0) red[threadIdx.x >> 5] = s;
    __syncthreads();
    if (threadIdx.x == 0)
        g_pooled[bc] = (red[0]+red[1]+red[2]+red[3]) * (1.0f/(NH*NW));
}

__global__ void route_kernel(const float* __restrict__ wr, const float* __restrict__ br) {
    int t = threadIdx.x;
    if (t >= NB*4) return;
    int b = t >> 2, e = t & 3;
    float acc = br[e];
    const float* pw = wr + e*NC;
    const float* pp = g_pooled + b*NC;
    #pragma unroll 8
    for (int c = 0; c < NC; ++c) acc = fmaf(pp[c], pw[c], acc);
    g_routing[t] = 1.f/(1.f + expf(-acc));
}

// weff[b][t][o][c] = tf32_rn( sum_e r[b,e] * W[e][o][c][t] )
__global__ void fold_kernel(const float* __restrict__ we) {
    int lin = blockIdx.x * blockDim.x + threadIdx.x;
    if (lin >= NTAP*NC*NC) return;
    int c = lin & 255, o = (lin >> 8) & 255, t = lin >> 16;
    size_t wi = ((size_t)o*NC + c)*NTAP + t;
    float w0 = we[wi], w1 = we[wi + (size_t)SEXP];
    float w2 = we[wi + 2*(size_t)SEXP], w3 = we[wi + 3*(size_t)SEXP];
    #pragma unroll
    for (int b = 0; b < NB; ++b) {
        const float* r = g_routing + b*4;
        g_weff[(((size_t)b*NTAP + t)*NC + o)*NC + c] =
            to_tf32(w0*r[0] + w1*r[1] + w2*r[2] + w3*r[3]);
    }
}

// x_pad[b][q][c], q over 66x66 padded grid, tf32 values, zero ring
__global__ void xpad_kernel(const float* __restrict__ x) {
    __shared__ float s[64*65];
    int c0 = blockIdx.x * 64, hp = blockIdx.y, b = blockIdx.z;
    int h = hp - 1;
    bool hv = (h >= 0 && h < NH);
    if (hv) {
        const float* xp = x + ((size_t)(b*NC + c0))*(NH*NW) + (size_t)h*NW;
        for (int j = 0; j < 16; ++j) {
            int idx = j*256 + threadIdx.x;
            int i = idx >> 6, w = idx & 63;
            s[w*65 + i] = to_tf32(xp[(size_t)i*(NH*NW) + w]);
        }
    }
    __syncthreads();
    float* op = g_xpad + ((size_t)b*QN + (size_t)hp*QP)*NC + c0;
    for (int j = 0; j < 17; ++j) {
        int idx = j*256 + threadIdx.x;
        if (idx >= QP*64) break;
        int i = idx & 63, wp = idx >> 6;
        float v = 0.f;
        if (hv && wp >= 1 && wp <= 64) v = s[(wp-1)*65 + i];
        op[(size_t)wp*NC + i] = v;
    }
}

// ------------------------------------------------------------------ conv GEMM
__device__ __forceinline__ void load_stage(uint32_t stBase, int step, int b,
                                           int o0, int q0, int tid)
{
    int t  = step >> 3;
    int c0 = (step & 7) * KC;
    int dh = t / 3, dw = t - dh*3;
    int qb = q0 + (dh-1)*QP + (dw-1);
    const float* aG = g_weff + (((size_t)(b*NTAP + t))*NC + o0)*NC + c0;
    const float* bG = g_xpad + (size_t)b*QN*NC + c0;
    // 3072 16B segments: A = 128 rows x 8, B = 256 rows x 8
    #pragma unroll
    for (int jj = 0; jj < 12; ++jj) {
        int seg = tid + jj*256;
        if (seg < 1024) {
            int row = seg >> 3, j = seg & 7;
            cp16(stBase + (row*ROWLEN + j*4)*4, aG + (size_t)row*NC + j*4, 16);
        } else {
            int k = seg - 1024;
            int row = k >> 3, j = k & 7;
            int q = qb + row;
            bool v = ((unsigned)q < (unsigned)QN);
            const float* src = bG + (size_t)(v ? q : 0)*NC + j*4;
            cp16(stBase + ((TILE_M + row)*ROWLEN + j*4)*4, src, v ? 16 : 0);
        }
    }
}

__global__ void __launch_bounds__(256)
conv_mma_kernel(const float* __restrict__ gamma, const float* __restrict__ beta,
                const float* __restrict__ mean,  const float* __restrict__ var,
                float* __restrict__ out)
{
    extern __shared__ __align__(128) float smem[];
    const uint32_t sb = s2u(smem);
    const int tid = threadIdx.x, wid = tid >> 5, lid = tid & 31;
    const int wm = wid >> 2, wn = wid & 3;        // warp grid 2 x 4
    const int g = lid >> 2, tig = lid & 3;
    const int b  = blockIdx.z;
    const int o0 = blockIdx.y * TILE_M;
    const int q0 = blockIdx.x * TILE_N;

    float acc[4][8][4];
    #pragma unroll
    for (int mi = 0; mi < 4; ++mi)
        #pragma unroll
        for (int ni = 0; ni < 8; ++ni)
            #pragma unroll
            for (int k = 0; k < 4; ++k) acc[mi][ni][k] = 0.f;

    load_stage(sb, 0, b, o0, q0, tid); cp_commit();
    load_stage(sb + STAGE_FLOATS*4, 1, b, o0, q0, tid); cp_commit();

    int buf = 0;
    #pragma unroll 1
    for (int s = 0; s < NSTEPS; ++s) {
        cp_wait<1>();
        __syncthreads();
        if (s + 2 < NSTEPS) {
            int nb = (buf + 2 >= STAGES) ? buf + 2 - STAGES : buf + 2;
            load_stage(sb + nb*STAGE_FLOATS*4, s + 2, b, o0, q0, tid);
        }
        cp_commit();   // commit even when empty to keep group counting uniform

        const float* sa = smem + buf*STAGE_FLOATS + (wm*64 + g)*ROWLEN + tig;
        const float* sB = smem + buf*STAGE_FLOATS + (TILE_M + wn*64 + g)*ROWLEN + tig;
        #pragma unroll
        for (int kk = 0; kk < 4; ++kk) {
            float a[4][4], bf[8][2];
            #pragma unroll
            for (int mi = 0; mi < 4; ++mi) {
                const float* p = sa + mi*16*ROWLEN + kk*8;
                a[mi][0] = p[0];
                a[mi][1] = p[8*ROWLEN];
                a[mi][2] = p[4];
                a[mi][3] = p[8*ROWLEN + 4];
            }
            #pragma unroll
            for (int ni = 0; ni < 8; ++ni) {
                const float* p = sB + ni*8*ROWLEN + kk*8;
                bf[ni][0] = p[0];
                bf[ni][1] = p[4];
            }
            #pragma unroll
            for (int mi = 0; mi < 4; ++mi)
                #pragma unroll
                for (int ni = 0; ni < 8; ++ni)
                    mma8(acc[mi][ni], a[mi], bf[ni]);
        }
        __syncthreads();
        buf = (buf + 1 >= STAGES) ? 0 : buf + 1;
    }

    // ---------------- epilogue: BN + SiLU + guarded stores
    float inv[4][2], add[4][2];
    #pragma unroll
    for (int mi = 0; mi < 4; ++mi)
        #pragma unroll
        for (int hi = 0; hi < 2; ++hi) {
            int o = o0 + wm*64 + mi*16 + g + hi*8;
            float iv = gamma[o] * rsqrtf(var[o] + 1e-5f);
            inv[mi][hi] = iv;
            add[mi][hi] = beta[o] - mean[o] * iv;
        }
    #pragma unroll
    for (int mi = 0; mi < 4; ++mi) {
        #pragma unroll
        for (int ni = 0; ni < 8; ++ni) {
            #pragma unroll
            for (int k = 0; k < 4; ++k) {
                int hi = k >> 1, c = k & 1;
                int q = q0 + wn*64 + ni*8 + 2*tig + c;
                int hp = q / QP, wp = q - hp*QP;
                if (q < QN && hp >= 1 && hp <= NH && wp >= 1 && wp <= NW) {
                    int o = o0 + wm*64 + mi*16 + g + hi*8;
                    float z = acc[mi][ni][k] * inv[mi][hi] + add[mi][hi];
                    out[(((size_t)b*NC + o)*NH + hp - 1)*NW + wp - 1] =
                        z / (1.f + expf(-z));
                }
            }
        }
    }
}

// ------------------------------------------------------------------ launch
extern "C" void kernel_launch(void* const* d_in, const int* in_sizes, int n_in,
                              void* d_out, int out_size) {
    const float* x        = (const float*)d_in[0];
    const float* w_route  = (const float*)d_in[1];
    const float* b_route  = (const float*)d_in[2];
    const float* w_expert = (const float*)d_in[3];
    const float* bn_gamma = (const float*)d_in[4];
    const float* bn_beta  = (const float*)d_in[5];
    const float* bn_mean  = (const float*)d_in[6];
    const float* bn_var   = (const float*)d_in[7];
    float* out = (float*)d_out;

    cudaFuncSetAttribute(conv_mma_kernel,
                         cudaFuncAttributeMaxDynamicSharedMemorySize, SMEM_TOTAL);

    pool_kernel<<<NB*NC, 128>>>(x);
    route_kernel<<<1, 64>>>(w_route, b_route);
    fold_kernel<<<(NTAP*NC*NC + 255)/256, 256>>>(w_expert);
    dim3 xg(NC/64, QP, NB);
    xpad_kernel<<<xg, 256>>>(x);
    dim3 grid(QTILES, NC/TILE_M, NB);
    conv_mma_kernel<<<grid, 256, SMEM_TOTAL>>>(bn_gamma, bn_beta, bn_mean, bn_var, out);
}

// round 5
// speedup vs baseline: 6.6467x; 1.0774x over previous
#include <cuda_runtime.h>
#include <math.h>
#include <stdint.h>

#define NB 16
#define NC 256
#define NH 64
#define NW 64
#define NTAP 9
#define SEXP (NC*NC*NTAP)
#define QP 66
#define QN (QP*QP)                /* 4356 padded pixels */
#define TILE_M 128
#define TILE_N 256
#define KC 32
#define NSTEPS (NTAP*(NC/KC))     /* 72 */
#define ROWLEN 36                 /* B row: 32 k + 4 pad floats */
#define A_FLOATS (TILE_M*KC)      /* 4096 (fragment-major, contiguous) */
#define B_FLOATS (TILE_N*ROWLEN)  /* 9216 */
#define STAGE_FLOATS (A_FLOATS + B_FLOATS)   /* 13312 */
#define STAGES 3
#define SMEM_TOTAL (STAGES * STAGE_FLOATS * 4)   /* 159744 B */
#define QTILES ((QN + TILE_N - 1) / TILE_N)      /* 18 */

__device__ float g_pooled[NB*NC];
__device__ float g_routing[NB*4];
// A, fragment-major: [b][t][otile(2)][chunk(8)][kk(4)][mblk(8)][lane(32)][v(4)]
__device__ __align__(1024) float g_weff[(size_t)NB*NTAP*NC*NC];
// B: [b][q][c] with channels permuted within each 8-group: pos = 2*tig + kv
__device__ __align__(1024) float g_xpad[(size_t)NB*QN*NC];

// ------------------------------------------------------------------ helpers
__device__ __forceinline__ uint32_t s2u(const void* p){
    uint32_t a;
    asm("{ .reg .u64 t; cvta.to.shared.u64 t, %1; cvt.u32.u64 %0, t; }" : "=r"(a) : "l"(p));
    return a;
}
__device__ __forceinline__ float to_tf32(float x){
    uint32_t r; asm("cvt.rna.tf32.f32 %0, %1;" : "=r"(r) : "f"(x));
    return __uint_as_float(r);
}
__device__ __forceinline__ void cp16(uint32_t dst, const void* src, int szbytes){
    asm volatile("cp.async.cg.shared.global [%0], [%1], 16, %2;"
                 :: "r"(dst), "l"(src), "r"(szbytes) : "memory");
}
__device__ __forceinline__ void cp_commit(){
    asm volatile("cp.async.commit_group;" ::: "memory");
}
template<int N> __device__ __forceinline__ void cp_wait(){
    asm volatile("cp.async.wait_group %0;" :: "n"(N) : "memory");
}
__device__ __forceinline__ void mma8(float* d, const float4 a, const float2 b){
    asm volatile("mma.sync.aligned.m16n8k8.row.col.f32.tf32.tf32.f32 "
        "{%0,%1,%2,%3}, {%4,%5,%6,%7}, {%8,%9}, {%0,%1,%2,%3};"
        : "+f"(d[0]), "+f"(d[1]), "+f"(d[2]), "+f"(d[3])
        : "r"(__float_as_uint(a.x)), "r"(__float_as_uint(a.y)),
          "r"(__float_as_uint(a.z)), "r"(__float_as_uint(a.w)),
          "r"(__float_as_uint(b.x)), "r"(__float_as_uint(b.y)));
}

// ------------------------------------------------------------------ prep
__global__ void pool_kernel(const float* __restrict__ x) {
    int bc = blockIdx.x;
    const float4* p = (const float4*)(x + (size_t)bc * NH * NW);
    float s = 0.f;
    for (int i = threadIdx.x; i < NH*NW/4; i += blockDim.x) {
        float4 v = p[i];
        s += v.x + v.y + v.z + v.w;
    }
    #pragma unroll
    for (int o = 16; o; o >>= 1) s += __shfl_xor_sync(0xffffffffu, s, o);
    __shared__ float red[4];
    if ((threadIdx.x & 31) == 0) red[threadIdx.x >> 5] = s;
    __syncthreads();
    if (threadIdx.x == 0)
        g_pooled[bc] = (red[0]+red[1]+red[2]+red[3]) * (1.0f/(NH*NW));
}

__global__ void route_kernel(const float* __restrict__ wr, const float* __restrict__ br) {
    int t = threadIdx.x;
    if (t >= NB*4) return;
    int b = t >> 2, e = t & 3;
    float acc = br[e];
    const float* pw = wr + e*NC;
    const float* pp = g_pooled + b*NC;
    #pragma unroll 8
    for (int c = 0; c < NC; ++c) acc = fmaf(pp[c], pw[c], acc);
    g_routing[t] = 1.f/(1.f + expf(-acc));
}

// weff fragment-major: thread (t,o,c) -> dst per m16n8k8 A-fragment mapping
__global__ void fold_kernel(const float* __restrict__ we) {
    int lin = blockIdx.x * blockDim.x + threadIdx.x;
    if (lin >= NTAP*NC*NC) return;
    int c = lin & 255, o = (lin >> 8) & 255, t = lin >> 16;
    size_t wi = ((size_t)o*NC + c)*NTAP + t;
    float w0 = we[wi], w1 = we[wi + (size_t)SEXP];
    float w2 = we[wi + 2*(size_t)SEXP], w3 = we[wi + 3*(size_t)SEXP];

    int chunk = c >> 5, kk = (c >> 3) & 3, tig = c & 3, kv = (c >> 2) & 1;
    int otile = o >> 7, mblk = (o >> 4) & 7, g = o & 7, hi = (o >> 3) & 1;
    int inner = ((kk*8 + mblk)*32 + g*4 + tig)*4 + (hi + 2*kv);
    size_t base = ((((size_t)t*2 + otile)*8 + chunk)*4096) + inner;   // per-b stride below
    #pragma unroll
    for (int b = 0; b < NB; ++b) {
        const float* r = g_routing + b*4;
        g_weff[(size_t)b*(NTAP*NC*NC) + base] =
            to_tf32(w0*r[0] + w1*r[1] + w2*r[2] + w3*r[3]);
    }
}

// x_pad[b][q][c_perm], q over 66x66 padded grid, tf32 values, zero ring.
// channel position within each 8-group: pos = 2*(k&3) + ((k>>2)&1)
__global__ void xpad_kernel(const float* __restrict__ x) {
    __shared__ float s[64*65];
    int c0 = blockIdx.x * 64, hp = blockIdx.y, b = blockIdx.z;
    int h = hp - 1;
    bool hv = (h >= 0 && h < NH);
    if (hv) {
        const float* xp = x + ((size_t)(b*NC + c0))*(NH*NW) + (size_t)h*NW;
        for (int j = 0; j < 16; ++j) {
            int idx = j*256 + threadIdx.x;
            int i = idx >> 6, w = idx & 63;
            s[w*65 + i] = to_tf32(xp[(size_t)i*(NH*NW) + w]);
        }
    }
    __syncthreads();
    float* op = g_xpad + ((size_t)b*QN + (size_t)hp*QP)*NC + c0;
    for (int j = 0; j < 17; ++j) {
        int idx = j*256 + threadIdx.x;
        if (idx >= QP*64) break;
        int i = idx & 63, wp = idx >> 6;
        float v = 0.f;
        if (hv && wp >= 1 && wp <= 64) v = s[(wp-1)*65 + i];
        int ipos = (i & ~7) | (((i & 3) << 1) | ((i >> 2) & 1));
        op[(size_t)wp*NC + ipos] = v;
    }
}

// ------------------------------------------------------------------ conv GEMM
__device__ __forceinline__ void load_stage(uint32_t stBase, int step, int b,
                                           int otile, int q0, int tid)
{
    int t  = step >> 3;
    int chunk = step & 7;
    int dh = t / 3, dw = t - dh*3;
    int qb = q0 + (dh-1)*QP + (dw-1);
    const float* aG = g_weff + (size_t)b*(NTAP*NC*NC)
                    + ((((size_t)t*2 + otile)*8 + chunk)*4096);
    const float* bG = g_xpad + (size_t)b*QN*NC + chunk*KC;
    // A: 1024 linear 16B segments (16 KB). B: 256 rows x 8 segments.
    #pragma unroll
    for (int jj = 0; jj < 12; ++jj) {
        int seg = tid + jj*256;
        if (seg < 1024) {
            cp16(stBase + seg*16, aG + seg*4, 16);
        } else {
            int k = seg - 1024;
            int row = k >> 3, j = k & 7;
            int q = qb + row;
            bool v = ((unsigned)q < (unsigned)QN);
            const float* src = bG + (size_t)(v ? q : 0)*NC + j*4;
            cp16(stBase + A_FLOATS*4 + (row*ROWLEN + j*4)*4, src, v ? 16 : 0);
        }
    }
}

__global__ void __launch_bounds__(256)
conv_mma_kernel(const float* __restrict__ gamma, const float* __restrict__ beta,
                const float* __restrict__ mean,  const float* __restrict__ var,
                float* __restrict__ out)
{
    extern __shared__ __align__(128) float smem[];
    const uint32_t sb = s2u(smem);
    const int tid = threadIdx.x, wid = tid >> 5, lid = tid & 31;
    const int wm = wid >> 2, wn = wid & 3;        // warp grid 2 x 4
    const int g = lid >> 2, tig = lid & 3;
    const int b  = blockIdx.z;
    const int otile = blockIdx.y;
    const int o0 = otile * TILE_M;
    const int q0 = blockIdx.x * TILE_N;

    float acc[4][8][4];
    #pragma unroll
    for (int mi = 0; mi < 4; ++mi)
        #pragma unroll
        for (int ni = 0; ni < 8; ++ni)
            #pragma unroll
            for (int k = 0; k < 4; ++k) acc[mi][ni][k] = 0.f;

    load_stage(sb, 0, b, otile, q0, tid); cp_commit();
    load_stage(sb + STAGE_FLOATS*4, 1, b, otile, q0, tid); cp_commit();

    int buf = 0;
    #pragma unroll 1
    for (int s = 0; s < NSTEPS; ++s) {
        cp_wait<1>();
        __syncthreads();
        if (s + 2 < NSTEPS) {
            int nb = (buf + 2 >= STAGES) ? buf + 2 - STAGES : buf + 2;
            load_stage(sb + nb*STAGE_FLOATS*4, s + 2, b, otile, q0, tid);
        }
        cp_commit();

        const float* sa = smem + buf*STAGE_FLOATS;
        const float* sB = smem + buf*STAGE_FLOATS + A_FLOATS
                        + (wn*64 + g)*ROWLEN + tig*2;
        #pragma unroll
        for (int kk = 0; kk < 4; ++kk) {
            float4 a[4];
            float2 bf[8];
            #pragma unroll
            for (int mi = 0; mi < 4; ++mi)
                a[mi] = *(const float4*)(sa + ((kk*8 + wm*4 + mi)*32 + lid)*4);
            #pragma unroll
            for (int ni = 0; ni < 8; ++ni)
                bf[ni] = *(const float2*)(sB + ni*8*ROWLEN + kk*8);
            #pragma unroll
            for (int mi = 0; mi < 4; ++mi)
                #pragma unroll
                for (int ni = 0; ni < 8; ++ni)
                    mma8(acc[mi][ni], a[mi], bf[ni]);
        }
        buf = (buf + 1 >= STAGES) ? 0 : buf + 1;
    }

    // ---------------- epilogue: BN + SiLU + guarded stores
    float inv[4][2], add[4][2];
    #pragma unroll
    for (int mi = 0; mi < 4; ++mi)
        #pragma unroll
        for (int hi = 0; hi < 2; ++hi) {
            int o = o0 + wm*64 + mi*16 + g + hi*8;
            float iv = gamma[o] * rsqrtf(var[o] + 1e-5f);
            inv[mi][hi] = iv;
            add[mi][hi] = beta[o] - mean[o] * iv;
        }
    #pragma unroll
    for (int mi = 0; mi < 4; ++mi) {
        #pragma unroll
        for (int ni = 0; ni < 8; ++ni) {
            #pragma unroll
            for (int k = 0; k < 4; ++k) {
                int hi = k >> 1, c = k & 1;
                int q = q0 + wn*64 + ni*8 + 2*tig + c;
                int hp = q / QP, wp = q - hp*QP;
                if (q < QN && hp >= 1 && hp <= NH && wp >= 1 && wp <= NW) {
                    int o = o0 + wm*64 + mi*16 + g + hi*8;
                    float z = acc[mi][ni][k] * inv[mi][hi] + add[mi][hi];
                    out[(((size_t)b*NC + o)*NH + hp - 1)*NW + wp - 1] =
                        z / (1.f + expf(-z));
                }
            }
        }
    }
}

// ------------------------------------------------------------------ launch
extern "C" void kernel_launch(void* const* d_in, const int* in_sizes, int n_in,
                              void* d_out, int out_size) {
    const float* x        = (const float*)d_in[0];
    const float* w_route  = (const float*)d_in[1];
    const float* b_route  = (const float*)d_in[2];
    const float* w_expert = (const float*)d_in[3];
    const float* bn_gamma = (const float*)d_in[4];
    const float* bn_beta  = (const float*)d_in[5];
    const float* bn_mean  = (const float*)d_in[6];
    const float* bn_var   = (const float*)d_in[7];
    float* out = (float*)d_out;

    cudaFuncSetAttribute(conv_mma_kernel,
                         cudaFuncAttributeMaxDynamicSharedMemorySize, SMEM_TOTAL);

    pool_kernel<<<NB*NC, 128>>>(x);
    route_kernel<<<1, 64>>>(w_route, b_route);
    fold_kernel<<<(NTAP*NC*NC + 255)/256, 256>>>(w_expert);
    dim3 xg(NC/64, QP, NB);
    xpad_kernel<<<xg, 256>>>(x);
    dim3 grid(QTILES, NC/TILE_M, NB);
    conv_mma_kernel<<<grid, 256, SMEM_TOTAL>>>(bn_gamma, bn_beta, bn_mean, bn_var, out);
}